// round 15
// baseline (speedup 1.0000x reference)
#include <cuda_runtime.h>
#include <cuda_fp16.h>
#include <math.h>
#include <stdint.h>

#define SZ 65535
#define THREADS 256
#define GRID 512

// ---- weight fragment image offsets (uint4 units), n2-major: [n2][kt][lane] ----
#define ENC_F   0        // 8 n2 x 16 kt x 32
#define WIHR_F  4096     // 8 n2 x 8 kt x 32
#define WIHZ_F  6144
#define WIHN_F  8192
#define WHHR_F  10240
#define WHHZ_F  12288
#define WHHN_F  14336
#define VW_F    16384    // 4 n2 x 8 kt x 32
#define DEC_F   17408    // 1 n2 x 12 kt x 32
#define FRAG_TOTAL 17792

__device__ __align__(16) uint4 g_bh[FRAG_TOTAL];

// ---- SMEM (bytes): 2 CTAs/SM ----
#define OFF_X    0        // 32KB: x (2 K blocks of 16KB), later h_out
#define OFF_H    32768    // 32KB: h; block0 later = v
#define OFF_OBS  65536    // 2 x 16KB obs slots (enc phase only)
#define OFF_BR   98304
#define OFF_BZ   98816
#define OFF_BIN  99328
#define OFF_BHN  99840
#define OFF_ENCB 100352
#define OFF_VB   100864
#define OFF_DECB 101120
#define SMEM_TOTAL 101376

#define SWZ(o) ((o) ^ (((o) >> 3) & 0x70))

__device__ __forceinline__ uint32_t smem_u32(const void* p) {
    uint32_t a;
    asm("{ .reg .u64 t; cvta.to.shared.u64 t, %1; cvt.u32.u64 %0, t; }" : "=r"(a) : "l"(p));
    return a;
}

__device__ __forceinline__ void ldm4(uint32_t r[4], uint32_t a) {
    asm volatile("ldmatrix.sync.aligned.m8n8.x4.shared.b16 {%0,%1,%2,%3}, [%4];"
        : "=r"(r[0]), "=r"(r[1]), "=r"(r[2]), "=r"(r[3]) : "r"(a));
}

__device__ __forceinline__ void mma_f16(float c[4], const uint32_t a[4], uint32_t b0, uint32_t b1) {
    asm volatile("mma.sync.aligned.m16n8k16.row.col.f32.f16.f16.f32 "
        "{%0,%1,%2,%3}, {%4,%5,%6,%7}, {%8,%9}, {%0,%1,%2,%3};"
        : "+f"(c[0]), "+f"(c[1]), "+f"(c[2]), "+f"(c[3])
        : "r"(a[0]), "r"(a[1]), "r"(a[2]), "r"(a[3]), "r"(b0), "r"(b1));
}

__device__ __forceinline__ uint32_t packh2(float a, float b) {
    __half2 h = __floats2half2_rn(a, b);
    return *(uint32_t*)&h;
}
__device__ __forceinline__ float h_lo(uint32_t v) {
    return __half2float(__ushort_as_half((unsigned short)(v & 0xFFFF)));
}
__device__ __forceinline__ float h_hi(uint32_t v) {
    return __half2float(__ushort_as_half((unsigned short)(v >> 16)));
}

// fast sigmoid: MUFU.EX2 + MUFU.RCP, no IEEE divide, no clamps (saturates naturally)
__device__ __forceinline__ float sigm(float x) {
    return __fdividef(1.f, 1.f + __expf(-x));
}
// tanh(x) = 2*sigmoid(2x) - 1  (register-light; abs err ~2e-7)
__device__ __forceinline__ float tanh_fast(float x) {
    return fmaf(2.f, sigm(2.f * x), -1.f);
}

// blocked K layout: 16KB per 64-col block (128 rows x 128B)
__device__ __forceinline__ void store_pair(char* region, int row, int col, float a, float b) {
    uint32_t off = (uint32_t)((col >> 6) * 16384) + SWZ((uint32_t)(row * 128 + (col & 63) * 2));
    *(uint32_t*)(region + off) = packh2(a, b);
}

// [128 rows x 64 cols] fp32 gmem tile -> fp16 swizzled plane
__device__ void conv_tile(const float* __restrict__ g, int stride, int col0, int row0g,
                          char* dst, int tid) {
#pragma unroll
    for (int i = 0; i < 4; i++) {
        int t = tid + i * 256;
        int r = t >> 3, gi = t & 7;
        int gr = row0g + r;
        uint4 P;
        if (gr < SZ) {
            float4 a = *(const float4*)(g + (size_t)gr * stride + col0 + gi * 8);
            float4 b = *(const float4*)(g + (size_t)gr * stride + col0 + gi * 8 + 4);
            P.x = packh2(a.x, a.y); P.y = packh2(a.z, a.w);
            P.z = packh2(b.x, b.y); P.w = packh2(b.z, b.w);
        } else {
            P.x = P.y = P.z = P.w = 0u;
        }
        *(uint4*)(dst + SWZ((uint32_t)(r * 128 + gi * 16))) = P;
    }
}

__device__ __forceinline__ void conv_load_pack(const float* __restrict__ g, int stride, int col0,
                                               int row0g, uint32_t st[16], int tid) {
#pragma unroll
    for (int i = 0; i < 4; i++) {
        int t = tid + i * 256;
        int r = t >> 3, gi = t & 7;
        int gr = row0g + r;
        if (gr < SZ) {
            float4 a = *(const float4*)(g + (size_t)gr * stride + col0 + gi * 8);
            float4 b = *(const float4*)(g + (size_t)gr * stride + col0 + gi * 8 + 4);
            st[i * 4 + 0] = packh2(a.x, a.y); st[i * 4 + 1] = packh2(a.z, a.w);
            st[i * 4 + 2] = packh2(b.x, b.y); st[i * 4 + 3] = packh2(b.z, b.w);
        } else {
            st[i * 4 + 0] = st[i * 4 + 1] = st[i * 4 + 2] = st[i * 4 + 3] = 0u;
        }
    }
}
__device__ __forceinline__ void conv_store16(char* dst, const uint32_t st[16], int tid) {
#pragma unroll
    for (int i = 0; i < 4; i++) {
        int t = tid + i * 256;
        int r = t >> 3, gi = t & 7;
        uint4 P = make_uint4(st[i * 4 + 0], st[i * 4 + 1], st[i * 4 + 2], st[i * 4 + 3]);
        *(uint4*)(dst + SWZ((uint32_t)(r * 128 + gi * 16))) = P;
    }
}

// ---------------- prep: pack weights as fp16 mma B-fragments (n2-major) ----------------
__global__ void prep_kernel(const float* __restrict__ enc_w, const float* __restrict__ w_ih,
                            const float* __restrict__ w_hh, const float* __restrict__ v_w,
                            const float* __restrict__ dec_w) {
    int idx = blockIdx.x * blockDim.x + threadIdx.x;
    if (idx >= FRAG_TOTAL) return;
    const float* W; int ldw, nmax, ktc, base;
    if (idx < 4096)       { W = enc_w; ldw = 256; nmax = 128; base = 0; ktc = 16; }
    else if (idx < 10240) { int g = (idx - 4096) / 2048; W = w_ih + (size_t)g * 128 * 128;
                            ldw = 128; nmax = 128; base = 4096 + g * 2048; ktc = 8; }
    else if (idx < 16384) { int g = (idx - 10240) / 2048; W = w_hh + (size_t)g * 128 * 128;
                            ldw = 128; nmax = 128; base = 10240 + g * 2048; ktc = 8; }
    else if (idx < 17408) { W = v_w; ldw = 128; nmax = 64; base = 16384; ktc = 8; }
    else                  { W = dec_w; ldw = 192; nmax = 10; base = 17408; ktc = 12; }

    int local = idx - base;
    int n2 = local / (ktc * 32);
    int rem = local - n2 * ktc * 32;
    int kt = rem >> 5, lane = rem & 31;
    int n = n2 * 16 + (lane >> 2);
    int k = kt * 16 + (lane & 3) * 2;

    float w[8];
#pragma unroll
    for (int dn = 0; dn < 2; dn++)
#pragma unroll
        for (int dk = 0; dk < 2; dk++)
#pragma unroll
            for (int e = 0; e < 2; e++) {
                int nn = n + dn * 8, kk = k + dk * 8 + e;
                w[(dn + dk * 2) * 2 + e] = (nn < nmax) ? W[(size_t)nn * ldw + kk] : 0.f;
            }
    uint4 H;
    H.x = packh2(w[0], w[1]);
    H.y = packh2(w[2], w[3]);
    H.z = packh2(w[4], w[5]);
    H.w = packh2(w[6], w[7]);
    g_bh[idx] = H;
}

// n16-pair mma group: 2 mmas
__device__ __forceinline__ void mma1(float cE[4], float cO[4], const uint32_t a[4], uint4 Bh) {
    mma_f16(cE, a, Bh.x, Bh.z);
    mma_f16(cO, a, Bh.y, Bh.w);
}

__device__ __forceinline__ void make_addrs(uint32_t areg, int arow, int kkp, uint32_t ad[8]) {
#pragma unroll
    for (int kt = 0; kt < 8; kt++) {
        int kk = kt * 16 + kkp;
        ad[kt] = areg + (uint32_t)((kk >> 6) * 16384) + SWZ((uint32_t)(arow * 128 + (kk & 63) * 2));
    }
}

#define ZERO244(a) { _Pragma("unroll") for (int _m = 0; _m < 2; _m++) _Pragma("unroll") for (int _i = 0; _i < 4; _i++) _Pragma("unroll") for (int _j = 0; _j < 4; _j++) (a)[_m][_i][_j] = 0.f; }

__global__ void __launch_bounds__(THREADS, 2)
ac_mma_kernel(const float* __restrict__ obs, const float* __restrict__ hid,
              const float* __restrict__ enc_b, const float* __restrict__ b_ih,
              const float* __restrict__ b_hh, const float* __restrict__ v_b,
              const float* __restrict__ dec_b,
              float* __restrict__ out, float* __restrict__ hout_g) {
    extern __shared__ char sm[];
    const uint32_t sbase = smem_u32(sm);
    const int tid = threadIdx.x, lane = tid & 31, wid = tid >> 5;
    const int wn = wid & 3, wm = wid >> 2;          // 2(M) x 4(N) warp grid
    const int row0 = blockIdx.x * 128;

    float* s_br   = (float*)(sm + OFF_BR);
    float* s_bz   = (float*)(sm + OFF_BZ);
    float* s_bin  = (float*)(sm + OFF_BIN);
    float* s_bhn  = (float*)(sm + OFF_BHN);
    float* s_encb = (float*)(sm + OFF_ENCB);
    float* s_vb   = (float*)(sm + OFF_VB);
    float* s_decb = (float*)(sm + OFF_DECB);

    if (tid < 128) {
        s_br[tid]   = b_ih[tid] + b_hh[tid];
        s_bz[tid]   = b_ih[128 + tid] + b_hh[128 + tid];
        s_bin[tid]  = b_ih[256 + tid];
        s_bhn[tid]  = b_hh[256 + tid];
        s_encb[tid] = enc_b[tid];
    }
    if (tid < 64) s_vb[tid]   = v_b[tid];
    if (tid < 16) s_decb[tid] = (tid < 10) ? dec_b[tid] : 0.f;

    // h -> fp16 plane (2 K blocks)
    conv_tile(hid, 128, 0,  row0, sm + OFF_H,         tid);
    conv_tile(hid, 128, 64, row0, sm + OFF_H + 16384, tid);

    const uint32_t xreg = sbase + OFF_X;
    const uint32_t hreg = sbase + OFF_H;
    const uint32_t oreg = sbase + OFF_OBS;
    const int kkp = (lane >> 4) << 3;

    // ======== enc GEMM: M=64/warp (mi=4), N=32/warp (2 n2), K=256 ========
    {
        float acc[4][4][4];
#pragma unroll
        for (int mi = 0; mi < 4; mi++)
#pragma unroll
            for (int ni = 0; ni < 4; ni++)
#pragma unroll
                for (int j = 0; j < 4; j++) acc[mi][ni][j] = 0.f;

        conv_tile(obs, 256, 0, row0, sm + OFF_OBS, tid);
        __syncthreads();

        uint32_t st[16];
        for (int kb = 0; kb < 4; kb++) {
            const uint32_t slotr = oreg + (uint32_t)((kb & 1) * 16384);
            if (kb < 3) conv_load_pack(obs, 256, (kb + 1) * 64, row0, st, tid);
#pragma unroll
            for (int kt4 = 0; kt4 < 4; kt4++) {
                int ktg = kb * 4 + kt4;
                uint4 B[2];
#pragma unroll
                for (int np = 0; np < 2; np++)
                    B[np] = g_bh[ENC_F + ((wn * 2 + np) * 16 + ktg) * 32 + lane];
                uint32_t a[4][4];
#pragma unroll
                for (int mi = 0; mi < 4; mi++) {
                    int arow = wm * 64 + mi * 16 + (lane & 15);
                    ldm4(a[mi], slotr + SWZ((uint32_t)(arow * 128 + (kt4 * 16 + kkp) * 2)));
                }
#pragma unroll
                for (int np = 0; np < 2; np++)
#pragma unroll
                    for (int mi = 0; mi < 4; mi++)
                        mma1(acc[mi][np * 2], acc[mi][np * 2 + 1], a[mi], B[np]);
            }
            if (kb < 3) conv_store16(sm + OFF_OBS + (((kb + 1) & 1) * 16384), st, tid);
            __syncthreads();
        }

        // x = relu(acc + b) -> s_x
#pragma unroll
        for (int mi = 0; mi < 4; mi++)
#pragma unroll
            for (int ni = 0; ni < 4; ni++) {
                int col = wn * 32 + ni * 8 + (lane & 3) * 2;
                float b0 = s_encb[col], b1 = s_encb[col + 1];
#pragma unroll
                for (int rp = 0; rp < 2; rp++) {
                    int row = wm * 64 + mi * 16 + (lane >> 2) + rp * 8;
                    store_pair(sm + OFF_X, row, col,
                               fmaxf(acc[mi][ni][rp * 2 + 0] + b0, 0.f),
                               fmaxf(acc[mi][ni][rp * 2 + 1] + b1, 0.f));
                }
            }
    }
    __syncthreads();

    // ======== GRU: two 64-row halves; M=32/warp (mi=2), N=32/warp ========
    for (int hp = 0; hp < 2; hp++) {
        uint32_t ax[2][8];
#pragma unroll
        for (int mi = 0; mi < 2; mi++)
            make_addrs(xreg, hp * 64 + wm * 32 + mi * 16 + (lane & 15), kkp, ax[mi]);
        // h source = ax + 32768

        // ---- pass A: r,z fused, sigma into registers ----
        uint32_t sr[2][8], zs[2][8];
        {
            float rg[2][4][4], zg[2][4][4];
            ZERO244(rg); ZERO244(zg);
#pragma unroll
            for (int src = 0; src < 2; src++) {
                const int fbr = src ? WHHR_F : WIHR_F;
                const int fbz = src ? WHHZ_F : WIHZ_F;
                const uint32_t off = src ? 32768u : 0u;
#pragma unroll
                for (int kt = 0; kt < 8; kt++) {
                    uint4 Br[2], Bz[2];
#pragma unroll
                    for (int np = 0; np < 2; np++) {
                        Br[np] = g_bh[fbr + ((wn * 2 + np) * 8 + kt) * 32 + lane];
                        Bz[np] = g_bh[fbz + ((wn * 2 + np) * 8 + kt) * 32 + lane];
                    }
                    uint32_t a[2][4];
#pragma unroll
                    for (int mi = 0; mi < 2; mi++) ldm4(a[mi], ax[mi][kt] + off);
#pragma unroll
                    for (int np = 0; np < 2; np++)
#pragma unroll
                        for (int mi = 0; mi < 2; mi++) {
                            mma1(rg[mi][np * 2], rg[mi][np * 2 + 1], a[mi], Br[np]);
                            mma1(zg[mi][np * 2], zg[mi][np * 2 + 1], a[mi], Bz[np]);
                        }
                }
            }
#pragma unroll
            for (int mi = 0; mi < 2; mi++)
#pragma unroll
                for (int ni = 0; ni < 4; ni++) {
                    int col = wn * 32 + ni * 8 + (lane & 3) * 2;
                    float br0 = s_br[col], br1 = s_br[col + 1];
                    float bz0 = s_bz[col], bz1 = s_bz[col + 1];
#pragma unroll
                    for (int rp = 0; rp < 2; rp++) {
                        sr[mi][ni * 2 + rp] = packh2(sigm(rg[mi][ni][rp * 2 + 0] + br0),
                                                     sigm(rg[mi][ni][rp * 2 + 1] + br1));
                        zs[mi][ni * 2 + rp] = packh2(sigm(zg[mi][ni][rp * 2 + 0] + bz0),
                                                     sigm(zg[mi][ni][rp * 2 + 1] + bz1));
                    }
                }
        }

        // ---- pass B: a_n (x), h_n (h) + epilogue ----
        {
            float an[2][4][4], hn[2][4][4];
            ZERO244(an); ZERO244(hn);
#pragma unroll
            for (int kt = 0; kt < 8; kt++) {
                uint4 Bi[2], Bh2[2];
#pragma unroll
                for (int np = 0; np < 2; np++) {
                    Bi[np]  = g_bh[WIHN_F + ((wn * 2 + np) * 8 + kt) * 32 + lane];
                    Bh2[np] = g_bh[WHHN_F + ((wn * 2 + np) * 8 + kt) * 32 + lane];
                }
#pragma unroll
                for (int mi = 0; mi < 2; mi++) {
                    uint32_t a[4], b[4];
                    ldm4(a, ax[mi][kt]);
                    ldm4(b, ax[mi][kt] + 32768u);
#pragma unroll
                    for (int np = 0; np < 2; np++) {
                        mma1(an[mi][np * 2], an[mi][np * 2 + 1], a, Bi[np]);
                        mma1(hn[mi][np * 2], hn[mi][np * 2 + 1], b, Bh2[np]);
                    }
                }
            }
            __syncthreads();   // all s_x/s_h reads of this half done before overwriting s_x

#pragma unroll
            for (int mi = 0; mi < 2; mi++)
#pragma unroll
                for (int ni = 0; ni < 4; ni++) {
                    int col = wn * 32 + ni * 8 + (lane & 3) * 2;
                    float bi0 = s_bin[col], bi1 = s_bin[col + 1];
                    float bh0 = s_bhn[col], bh1 = s_bhn[col + 1];
#pragma unroll
                    for (int rp = 0; rp < 2; rp++) {
                        int row = hp * 64 + wm * 32 + mi * 16 + (lane >> 2) + rp * 8;
                        int grow = row0 + row;
                        float h0 = 0.f, h1 = 0.f;
                        if (grow < SZ) {
                            float2 t = *(const float2*)(hid + (size_t)grow * 128 + col);
                            h0 = t.x; h1 = t.y;
                        }
                        float r0 = h_lo(sr[mi][ni * 2 + rp]), r1 = h_hi(sr[mi][ni * 2 + rp]);
                        float z0 = h_lo(zs[mi][ni * 2 + rp]), z1 = h_hi(zs[mi][ni * 2 + rp]);
                        float n0 = tanh_fast(fmaf(r0, hn[mi][ni][rp * 2 + 0] + bh0,
                                                  an[mi][ni][rp * 2 + 0] + bi0));
                        float n1 = tanh_fast(fmaf(r1, hn[mi][ni][rp * 2 + 1] + bh1,
                                                  an[mi][ni][rp * 2 + 1] + bi1));
                        float o0 = fmaf(z0, h0 - n0, n0);
                        float o1 = fmaf(z1, h1 - n1, n1);
                        if (grow < SZ)
                            *(float2*)(hout_g + (size_t)grow * 128 + col) = make_float2(o0, o1);
                        store_pair(sm + OFF_X, row, col, o0, o1);
                    }
                }
        }
        __syncthreads();
    }

    // ======== v GEMM: M=64/warp (mi=4), N=16/warp, K=128 ========
    {
        float vc[4][2][4];
#pragma unroll
        for (int mi = 0; mi < 4; mi++)
#pragma unroll
            for (int e = 0; e < 2; e++)
#pragma unroll
                for (int j = 0; j < 4; j++) vc[mi][e][j] = 0.f;
#pragma unroll
        for (int kt = 0; kt < 8; kt++) {
            int kk = kt * 16 + kkp;
            uint4 B = g_bh[VW_F + (wn * 8 + kt) * 32 + lane];
            uint32_t a[4][4];
#pragma unroll
            for (int mi = 0; mi < 4; mi++) {
                int arow = wm * 64 + mi * 16 + (lane & 15);
                ldm4(a[mi], xreg + (uint32_t)((kk >> 6) * 16384) + SWZ((uint32_t)(arow * 128 + (kk & 63) * 2)));
            }
#pragma unroll
            for (int mi = 0; mi < 4; mi++)
                mma1(vc[mi][0], vc[mi][1], a[mi], B);
        }
        // v -> s_h block 0
#pragma unroll
        for (int mi = 0; mi < 4; mi++)
#pragma unroll
            for (int e = 0; e < 2; e++) {
                int col = wn * 16 + e * 8 + (lane & 3) * 2;
                float b0 = s_vb[col], b1 = s_vb[col + 1];
#pragma unroll
                for (int rp = 0; rp < 2; rp++) {
                    int row = wm * 64 + mi * 16 + (lane >> 2) + rp * 8;
                    store_pair(sm + OFF_H, row, col,
                               fmaxf(vc[mi][e][rp * 2 + 0] + b0, 0.f),
                               fmaxf(vc[mi][e][rp * 2 + 1] + b1, 0.f));
                }
            }
    }
    __syncthreads();

    // ======== dec GEMM: each warp 16 rows, N=16, K=192 ========
    {
        float dcE[4], dcO[4];
#pragma unroll
        for (int j = 0; j < 4; j++) { dcE[j] = 0.f; dcO[j] = 0.f; }
        const int arow = wid * 16 + (lane & 15);
#pragma unroll
        for (int kt = 0; kt < 12; kt++) {
            uint32_t areg2 = (kt < 8) ? xreg : hreg;
            int kk = ((kt < 8) ? kt : (kt - 8)) * 16 + kkp;
            uint4 Bh = g_bh[DEC_F + kt * 32 + lane];
            uint32_t a[4];
            ldm4(a, areg2 + (uint32_t)((kk >> 6) * 16384) + SWZ((uint32_t)(arow * 128 + (kk & 63) * 2)));
            mma1(dcE, dcO, a, Bh);
        }
        int colE = (lane & 3) * 2;
        int colO = 8 + (lane & 3) * 2;
        float bE0 = s_decb[colE], bE1 = s_decb[colE + 1];
        float bO0 = s_decb[colO], bO1 = s_decb[colO + 1];
#pragma unroll
        for (int rp = 0; rp < 2; rp++) {
            int row = wid * 16 + (lane >> 2) + rp * 8;
            int grow = row0 + row;
            if (grow < SZ) {
                float* o = out + (size_t)grow * 10;
                o[colE] = dcE[rp * 2 + 0] + bE0;
                o[colE + 1] = dcE[rp * 2 + 1] + bE1;
                if (colO < 10)     o[colO] = dcO[rp * 2 + 0] + bO0;
                if (colO + 1 < 10) o[colO + 1] = dcO[rp * 2 + 1] + bO1;
            }
        }
    }
}

extern "C" void kernel_launch(void* const* d_in, const int* in_sizes, int n_in,
                              void* d_out, int out_size) {
    const float* obs   = (const float*)d_in[0];
    const float* hid   = (const float*)d_in[1];
    const float* enc_w = (const float*)d_in[2];
    const float* enc_b = (const float*)d_in[3];
    const float* w_ih  = (const float*)d_in[4];
    const float* w_hh  = (const float*)d_in[5];
    const float* b_ih  = (const float*)d_in[6];
    const float* b_hh  = (const float*)d_in[7];
    const float* v_w   = (const float*)d_in[20];
    const float* v_b   = (const float*)d_in[21];
    const float* dec_w = (const float*)d_in[22];
    const float* dec_b = (const float*)d_in[23];

    float* out  = (float*)d_out;
    float* hout = out + (size_t)SZ * 10;

    prep_kernel<<<(FRAG_TOTAL + 255) / 256, 256>>>(enc_w, w_ih, w_hh, v_w, dec_w);

    cudaFuncSetAttribute(ac_mma_kernel, cudaFuncAttributeMaxDynamicSharedMemorySize, SMEM_TOTAL);
    ac_mma_kernel<<<GRID, THREADS, SMEM_TOTAL>>>(obs, hid, enc_b, b_ih, b_hh, v_b, dec_b, out, hout);
}

// round 16
// speedup vs baseline: 1.5639x; 1.5639x over previous
#include <cuda_runtime.h>
#include <cuda_fp16.h>
#include <math.h>
#include <stdint.h>

#define SZ 65535
#define THREADS 256
#define GRID 512

// ---- weight fragment image offsets (uint4 units), n2-major: [n2][kt][lane] ----
#define ENC_F   0        // 8 n2 x 16 kt x 32
#define WIHR_F  4096     // 8 n2 x 8 kt x 32
#define WIHZ_F  6144
#define WIHN_F  8192
#define WHHR_F  10240
#define WHHZ_F  12288
#define WHHN_F  14336
#define VW_F    16384    // 4 n2 x 8 kt x 32
#define DEC_F   17408    // 1 n2 x 12 kt x 32
#define FRAG_TOTAL 17792

__device__ __align__(16) uint4 g_bh[FRAG_TOTAL];

// ---- SMEM (bytes): 2 CTAs/SM ----
#define OFF_X    0        // 32KB: x (2 K blocks of 16KB), later h_out
#define OFF_H    32768    // 32KB: h; block0 later = v
#define OFF_OBS  65536    // 2 x 16KB obs slots (enc phase only)
#define OFF_BR   98304
#define OFF_BZ   98816
#define OFF_BIN  99328
#define OFF_BHN  99840
#define OFF_ENCB 100352
#define OFF_VB   100864
#define OFF_DECB 101120
#define SMEM_TOTAL 101376

#define SWZ(o) ((o) ^ (((o) >> 3) & 0x70))

__device__ __forceinline__ uint32_t smem_u32(const void* p) {
    uint32_t a;
    asm("{ .reg .u64 t; cvta.to.shared.u64 t, %1; cvt.u32.u64 %0, t; }" : "=r"(a) : "l"(p));
    return a;
}

__device__ __forceinline__ void ldm4(uint32_t r[4], uint32_t a) {
    asm volatile("ldmatrix.sync.aligned.m8n8.x4.shared.b16 {%0,%1,%2,%3}, [%4];"
        : "=r"(r[0]), "=r"(r[1]), "=r"(r[2]), "=r"(r[3]) : "r"(a));
}

__device__ __forceinline__ void mma_f16(float c[4], const uint32_t a[4], uint32_t b0, uint32_t b1) {
    asm volatile("mma.sync.aligned.m16n8k16.row.col.f32.f16.f16.f32 "
        "{%0,%1,%2,%3}, {%4,%5,%6,%7}, {%8,%9}, {%0,%1,%2,%3};"
        : "+f"(c[0]), "+f"(c[1]), "+f"(c[2]), "+f"(c[3])
        : "r"(a[0]), "r"(a[1]), "r"(a[2]), "r"(a[3]), "r"(b0), "r"(b1));
}

__device__ __forceinline__ uint32_t packh2(float a, float b) {
    __half2 h = __floats2half2_rn(a, b);
    return *(uint32_t*)&h;
}
__device__ __forceinline__ float h_lo(uint32_t v) {
    return __half2float(__ushort_as_half((unsigned short)(v & 0xFFFF)));
}
__device__ __forceinline__ float h_hi(uint32_t v) {
    return __half2float(__ushort_as_half((unsigned short)(v >> 16)));
}

// sigmoid exactly as R13 (known non-spilling)
__device__ __forceinline__ float sigm(float x) { return 1.f / (1.f + __expf(-x)); }

// single-instruction tanh: MUFU.TANH (sm_75+). One dest reg, no schedulable chain.
__device__ __forceinline__ float tanh_fast(float x) {
    float y;
    asm("tanh.approx.f32 %0, %1;" : "=f"(y) : "f"(x));
    return y;
}

// blocked K layout: 16KB per 64-col block (128 rows x 128B)
__device__ __forceinline__ void store_pair(char* region, int row, int col, float a, float b) {
    uint32_t off = (uint32_t)((col >> 6) * 16384) + SWZ((uint32_t)(row * 128 + (col & 63) * 2));
    *(uint32_t*)(region + off) = packh2(a, b);
}

// [128 rows x 64 cols] fp32 gmem tile -> fp16 swizzled plane
__device__ void conv_tile(const float* __restrict__ g, int stride, int col0, int row0g,
                          char* dst, int tid) {
#pragma unroll
    for (int i = 0; i < 4; i++) {
        int t = tid + i * 256;
        int r = t >> 3, gi = t & 7;
        int gr = row0g + r;
        uint4 P;
        if (gr < SZ) {
            float4 a = *(const float4*)(g + (size_t)gr * stride + col0 + gi * 8);
            float4 b = *(const float4*)(g + (size_t)gr * stride + col0 + gi * 8 + 4);
            P.x = packh2(a.x, a.y); P.y = packh2(a.z, a.w);
            P.z = packh2(b.x, b.y); P.w = packh2(b.z, b.w);
        } else {
            P.x = P.y = P.z = P.w = 0u;
        }
        *(uint4*)(dst + SWZ((uint32_t)(r * 128 + gi * 16))) = P;
    }
}

__device__ __forceinline__ void conv_load_pack(const float* __restrict__ g, int stride, int col0,
                                               int row0g, uint32_t st[16], int tid) {
#pragma unroll
    for (int i = 0; i < 4; i++) {
        int t = tid + i * 256;
        int r = t >> 3, gi = t & 7;
        int gr = row0g + r;
        if (gr < SZ) {
            float4 a = *(const float4*)(g + (size_t)gr * stride + col0 + gi * 8);
            float4 b = *(const float4*)(g + (size_t)gr * stride + col0 + gi * 8 + 4);
            st[i * 4 + 0] = packh2(a.x, a.y); st[i * 4 + 1] = packh2(a.z, a.w);
            st[i * 4 + 2] = packh2(b.x, b.y); st[i * 4 + 3] = packh2(b.z, b.w);
        } else {
            st[i * 4 + 0] = st[i * 4 + 1] = st[i * 4 + 2] = st[i * 4 + 3] = 0u;
        }
    }
}
__device__ __forceinline__ void conv_store16(char* dst, const uint32_t st[16], int tid) {
#pragma unroll
    for (int i = 0; i < 4; i++) {
        int t = tid + i * 256;
        int r = t >> 3, gi = t & 7;
        uint4 P = make_uint4(st[i * 4 + 0], st[i * 4 + 1], st[i * 4 + 2], st[i * 4 + 3]);
        *(uint4*)(dst + SWZ((uint32_t)(r * 128 + gi * 16))) = P;
    }
}

// ---------------- prep: pack weights as fp16 mma B-fragments (n2-major) ----------------
__global__ void prep_kernel(const float* __restrict__ enc_w, const float* __restrict__ w_ih,
                            const float* __restrict__ w_hh, const float* __restrict__ v_w,
                            const float* __restrict__ dec_w) {
    int idx = blockIdx.x * blockDim.x + threadIdx.x;
    if (idx >= FRAG_TOTAL) return;
    const float* W; int ldw, nmax, ktc, base;
    if (idx < 4096)       { W = enc_w; ldw = 256; nmax = 128; base = 0; ktc = 16; }
    else if (idx < 10240) { int g = (idx - 4096) / 2048; W = w_ih + (size_t)g * 128 * 128;
                            ldw = 128; nmax = 128; base = 4096 + g * 2048; ktc = 8; }
    else if (idx < 16384) { int g = (idx - 10240) / 2048; W = w_hh + (size_t)g * 128 * 128;
                            ldw = 128; nmax = 128; base = 10240 + g * 2048; ktc = 8; }
    else if (idx < 17408) { W = v_w; ldw = 128; nmax = 64; base = 16384; ktc = 8; }
    else                  { W = dec_w; ldw = 192; nmax = 10; base = 17408; ktc = 12; }

    int local = idx - base;
    int n2 = local / (ktc * 32);
    int rem = local - n2 * ktc * 32;
    int kt = rem >> 5, lane = rem & 31;
    int n = n2 * 16 + (lane >> 2);
    int k = kt * 16 + (lane & 3) * 2;

    float w[8];
#pragma unroll
    for (int dn = 0; dn < 2; dn++)
#pragma unroll
        for (int dk = 0; dk < 2; dk++)
#pragma unroll
            for (int e = 0; e < 2; e++) {
                int nn = n + dn * 8, kk = k + dk * 8 + e;
                w[(dn + dk * 2) * 2 + e] = (nn < nmax) ? W[(size_t)nn * ldw + kk] : 0.f;
            }
    uint4 H;
    H.x = packh2(w[0], w[1]);
    H.y = packh2(w[2], w[3]);
    H.z = packh2(w[4], w[5]);
    H.w = packh2(w[6], w[7]);
    g_bh[idx] = H;
}

// n16-pair mma group: 2 mmas
__device__ __forceinline__ void mma1(float cE[4], float cO[4], const uint32_t a[4], uint4 Bh) {
    mma_f16(cE, a, Bh.x, Bh.z);
    mma_f16(cO, a, Bh.y, Bh.w);
}

__device__ __forceinline__ void make_addrs(uint32_t areg, int arow, int kkp, uint32_t ad[8]) {
#pragma unroll
    for (int kt = 0; kt < 8; kt++) {
        int kk = kt * 16 + kkp;
        ad[kt] = areg + (uint32_t)((kk >> 6) * 16384) + SWZ((uint32_t)(arow * 128 + (kk & 63) * 2));
    }
}

#define ZERO244(a) { _Pragma("unroll") for (int _m = 0; _m < 2; _m++) _Pragma("unroll") for (int _i = 0; _i < 4; _i++) _Pragma("unroll") for (int _j = 0; _j < 4; _j++) (a)[_m][_i][_j] = 0.f; }

__global__ void __launch_bounds__(THREADS, 2)
ac_mma_kernel(const float* __restrict__ obs, const float* __restrict__ hid,
              const float* __restrict__ enc_b, const float* __restrict__ b_ih,
              const float* __restrict__ b_hh, const float* __restrict__ v_b,
              const float* __restrict__ dec_b,
              float* __restrict__ out, float* __restrict__ hout_g) {
    extern __shared__ char sm[];
    const uint32_t sbase = smem_u32(sm);
    const int tid = threadIdx.x, lane = tid & 31, wid = tid >> 5;
    const int wn = wid & 3, wm = wid >> 2;          // 2(M) x 4(N) warp grid
    const int row0 = blockIdx.x * 128;

    float* s_br   = (float*)(sm + OFF_BR);
    float* s_bz   = (float*)(sm + OFF_BZ);
    float* s_bin  = (float*)(sm + OFF_BIN);
    float* s_bhn  = (float*)(sm + OFF_BHN);
    float* s_encb = (float*)(sm + OFF_ENCB);
    float* s_vb   = (float*)(sm + OFF_VB);
    float* s_decb = (float*)(sm + OFF_DECB);

    if (tid < 128) {
        s_br[tid]   = b_ih[tid] + b_hh[tid];
        s_bz[tid]   = b_ih[128 + tid] + b_hh[128 + tid];
        s_bin[tid]  = b_ih[256 + tid];
        s_bhn[tid]  = b_hh[256 + tid];
        s_encb[tid] = enc_b[tid];
    }
    if (tid < 64) s_vb[tid]   = v_b[tid];
    if (tid < 16) s_decb[tid] = (tid < 10) ? dec_b[tid] : 0.f;

    // h -> fp16 plane (2 K blocks)
    conv_tile(hid, 128, 0,  row0, sm + OFF_H,         tid);
    conv_tile(hid, 128, 64, row0, sm + OFF_H + 16384, tid);

    const uint32_t xreg = sbase + OFF_X;
    const uint32_t hreg = sbase + OFF_H;
    const uint32_t oreg = sbase + OFF_OBS;
    const int kkp = (lane >> 4) << 3;

    // ======== enc GEMM: M=64/warp (mi=4), N=32/warp (2 n2), K=256 ========
    {
        float acc[4][4][4];
#pragma unroll
        for (int mi = 0; mi < 4; mi++)
#pragma unroll
            for (int ni = 0; ni < 4; ni++)
#pragma unroll
                for (int j = 0; j < 4; j++) acc[mi][ni][j] = 0.f;

        conv_tile(obs, 256, 0, row0, sm + OFF_OBS, tid);
        __syncthreads();

        uint32_t st[16];
        for (int kb = 0; kb < 4; kb++) {
            const uint32_t slotr = oreg + (uint32_t)((kb & 1) * 16384);
            if (kb < 3) conv_load_pack(obs, 256, (kb + 1) * 64, row0, st, tid);
#pragma unroll
            for (int kt4 = 0; kt4 < 4; kt4++) {
                int ktg = kb * 4 + kt4;
                uint4 B[2];
#pragma unroll
                for (int np = 0; np < 2; np++)
                    B[np] = g_bh[ENC_F + ((wn * 2 + np) * 16 + ktg) * 32 + lane];
                uint32_t a[4][4];
#pragma unroll
                for (int mi = 0; mi < 4; mi++) {
                    int arow = wm * 64 + mi * 16 + (lane & 15);
                    ldm4(a[mi], slotr + SWZ((uint32_t)(arow * 128 + (kt4 * 16 + kkp) * 2)));
                }
#pragma unroll
                for (int np = 0; np < 2; np++)
#pragma unroll
                    for (int mi = 0; mi < 4; mi++)
                        mma1(acc[mi][np * 2], acc[mi][np * 2 + 1], a[mi], B[np]);
            }
            if (kb < 3) conv_store16(sm + OFF_OBS + (((kb + 1) & 1) * 16384), st, tid);
            __syncthreads();
        }

        // x = relu(acc + b) -> s_x
#pragma unroll
        for (int mi = 0; mi < 4; mi++)
#pragma unroll
            for (int ni = 0; ni < 4; ni++) {
                int col = wn * 32 + ni * 8 + (lane & 3) * 2;
                float b0 = s_encb[col], b1 = s_encb[col + 1];
#pragma unroll
                for (int rp = 0; rp < 2; rp++) {
                    int row = wm * 64 + mi * 16 + (lane >> 2) + rp * 8;
                    store_pair(sm + OFF_X, row, col,
                               fmaxf(acc[mi][ni][rp * 2 + 0] + b0, 0.f),
                               fmaxf(acc[mi][ni][rp * 2 + 1] + b1, 0.f));
                }
            }
    }
    __syncthreads();

    // ======== GRU: two 64-row halves; M=32/warp (mi=2), N=32/warp ========
    for (int hp = 0; hp < 2; hp++) {
        uint32_t ax[2][8];
#pragma unroll
        for (int mi = 0; mi < 2; mi++)
            make_addrs(xreg, hp * 64 + wm * 32 + mi * 16 + (lane & 15), kkp, ax[mi]);
        // h source = ax + 32768

        // ---- pass A: r,z fused, sigma into registers ----
        uint32_t sr[2][8], zs[2][8];
        {
            float rg[2][4][4], zg[2][4][4];
            ZERO244(rg); ZERO244(zg);
#pragma unroll
            for (int src = 0; src < 2; src++) {
                const int fbr = src ? WHHR_F : WIHR_F;
                const int fbz = src ? WHHZ_F : WIHZ_F;
                const uint32_t off = src ? 32768u : 0u;
#pragma unroll
                for (int kt = 0; kt < 8; kt++) {
                    uint4 Br[2], Bz[2];
#pragma unroll
                    for (int np = 0; np < 2; np++) {
                        Br[np] = g_bh[fbr + ((wn * 2 + np) * 8 + kt) * 32 + lane];
                        Bz[np] = g_bh[fbz + ((wn * 2 + np) * 8 + kt) * 32 + lane];
                    }
                    uint32_t a[2][4];
#pragma unroll
                    for (int mi = 0; mi < 2; mi++) ldm4(a[mi], ax[mi][kt] + off);
#pragma unroll
                    for (int np = 0; np < 2; np++)
#pragma unroll
                        for (int mi = 0; mi < 2; mi++) {
                            mma1(rg[mi][np * 2], rg[mi][np * 2 + 1], a[mi], Br[np]);
                            mma1(zg[mi][np * 2], zg[mi][np * 2 + 1], a[mi], Bz[np]);
                        }
                }
            }
#pragma unroll
            for (int mi = 0; mi < 2; mi++)
#pragma unroll
                for (int ni = 0; ni < 4; ni++) {
                    int col = wn * 32 + ni * 8 + (lane & 3) * 2;
                    float br0 = s_br[col], br1 = s_br[col + 1];
                    float bz0 = s_bz[col], bz1 = s_bz[col + 1];
#pragma unroll
                    for (int rp = 0; rp < 2; rp++) {
                        sr[mi][ni * 2 + rp] = packh2(sigm(rg[mi][ni][rp * 2 + 0] + br0),
                                                     sigm(rg[mi][ni][rp * 2 + 1] + br1));
                        zs[mi][ni * 2 + rp] = packh2(sigm(zg[mi][ni][rp * 2 + 0] + bz0),
                                                     sigm(zg[mi][ni][rp * 2 + 1] + bz1));
                    }
                }
        }

        // ---- pass B: a_n (x), h_n (h) + epilogue ----
        {
            float an[2][4][4], hn[2][4][4];
            ZERO244(an); ZERO244(hn);
#pragma unroll
            for (int kt = 0; kt < 8; kt++) {
                uint4 Bi[2], Bh2[2];
#pragma unroll
                for (int np = 0; np < 2; np++) {
                    Bi[np]  = g_bh[WIHN_F + ((wn * 2 + np) * 8 + kt) * 32 + lane];
                    Bh2[np] = g_bh[WHHN_F + ((wn * 2 + np) * 8 + kt) * 32 + lane];
                }
#pragma unroll
                for (int mi = 0; mi < 2; mi++) {
                    uint32_t a[4], b[4];
                    ldm4(a, ax[mi][kt]);
                    ldm4(b, ax[mi][kt] + 32768u);
#pragma unroll
                    for (int np = 0; np < 2; np++) {
                        mma1(an[mi][np * 2], an[mi][np * 2 + 1], a, Bi[np]);
                        mma1(hn[mi][np * 2], hn[mi][np * 2 + 1], b, Bh2[np]);
                    }
                }
            }
            __syncthreads();   // all s_x/s_h reads of this half done before overwriting s_x

#pragma unroll
            for (int mi = 0; mi < 2; mi++)
#pragma unroll
                for (int ni = 0; ni < 4; ni++) {
                    int col = wn * 32 + ni * 8 + (lane & 3) * 2;
                    float bi0 = s_bin[col], bi1 = s_bin[col + 1];
                    float bh0 = s_bhn[col], bh1 = s_bhn[col + 1];
#pragma unroll
                    for (int rp = 0; rp < 2; rp++) {
                        int row = hp * 64 + wm * 32 + mi * 16 + (lane >> 2) + rp * 8;
                        int grow = row0 + row;
                        float h0 = 0.f, h1 = 0.f;
                        if (grow < SZ) {
                            float2 t = *(const float2*)(hid + (size_t)grow * 128 + col);
                            h0 = t.x; h1 = t.y;
                        }
                        float r0 = h_lo(sr[mi][ni * 2 + rp]), r1 = h_hi(sr[mi][ni * 2 + rp]);
                        float z0 = h_lo(zs[mi][ni * 2 + rp]), z1 = h_hi(zs[mi][ni * 2 + rp]);
                        float n0 = tanh_fast(an[mi][ni][rp * 2 + 0] + bi0 + r0 * (hn[mi][ni][rp * 2 + 0] + bh0));
                        float n1 = tanh_fast(an[mi][ni][rp * 2 + 1] + bi1 + r1 * (hn[mi][ni][rp * 2 + 1] + bh1));
                        float o0 = (1.f - z0) * n0 + z0 * h0;
                        float o1 = (1.f - z1) * n1 + z1 * h1;
                        if (grow < SZ)
                            *(float2*)(hout_g + (size_t)grow * 128 + col) = make_float2(o0, o1);
                        store_pair(sm + OFF_X, row, col, o0, o1);
                    }
                }
        }
        __syncthreads();
    }

    // ======== v GEMM: M=64/warp (mi=4), N=16/warp, K=128 ========
    {
        float vc[4][2][4];
#pragma unroll
        for (int mi = 0; mi < 4; mi++)
#pragma unroll
            for (int e = 0; e < 2; e++)
#pragma unroll
                for (int j = 0; j < 4; j++) vc[mi][e][j] = 0.f;
#pragma unroll
        for (int kt = 0; kt < 8; kt++) {
            int kk = kt * 16 + kkp;
            uint4 B = g_bh[VW_F + (wn * 8 + kt) * 32 + lane];
            uint32_t a[4][4];
#pragma unroll
            for (int mi = 0; mi < 4; mi++) {
                int arow = wm * 64 + mi * 16 + (lane & 15);
                ldm4(a[mi], xreg + (uint32_t)((kk >> 6) * 16384) + SWZ((uint32_t)(arow * 128 + (kk & 63) * 2)));
            }
#pragma unroll
            for (int mi = 0; mi < 4; mi++)
                mma1(vc[mi][0], vc[mi][1], a[mi], B);
        }
        // v -> s_h block 0
#pragma unroll
        for (int mi = 0; mi < 4; mi++)
#pragma unroll
            for (int e = 0; e < 2; e++) {
                int col = wn * 16 + e * 8 + (lane & 3) * 2;
                float b0 = s_vb[col], b1 = s_vb[col + 1];
#pragma unroll
                for (int rp = 0; rp < 2; rp++) {
                    int row = wm * 64 + mi * 16 + (lane >> 2) + rp * 8;
                    store_pair(sm + OFF_H, row, col,
                               fmaxf(vc[mi][e][rp * 2 + 0] + b0, 0.f),
                               fmaxf(vc[mi][e][rp * 2 + 1] + b1, 0.f));
                }
            }
    }
    __syncthreads();

    // ======== dec GEMM: each warp 16 rows, N=16, K=192 ========
    {
        float dcE[4], dcO[4];
#pragma unroll
        for (int j = 0; j < 4; j++) { dcE[j] = 0.f; dcO[j] = 0.f; }
        const int arow = wid * 16 + (lane & 15);
#pragma unroll
        for (int kt = 0; kt < 12; kt++) {
            uint32_t areg2 = (kt < 8) ? xreg : hreg;
            int kk = ((kt < 8) ? kt : (kt - 8)) * 16 + kkp;
            uint4 Bh = g_bh[DEC_F + kt * 32 + lane];
            uint32_t a[4];
            ldm4(a, areg2 + (uint32_t)((kk >> 6) * 16384) + SWZ((uint32_t)(arow * 128 + (kk & 63) * 2)));
            mma1(dcE, dcO, a, Bh);
        }
        int colE = (lane & 3) * 2;
        int colO = 8 + (lane & 3) * 2;
        float bE0 = s_decb[colE], bE1 = s_decb[colE + 1];
        float bO0 = s_decb[colO], bO1 = s_decb[colO + 1];
#pragma unroll
        for (int rp = 0; rp < 2; rp++) {
            int row = wid * 16 + (lane >> 2) + rp * 8;
            int grow = row0 + row;
            if (grow < SZ) {
                float* o = out + (size_t)grow * 10;
                o[colE] = dcE[rp * 2 + 0] + bE0;
                o[colE + 1] = dcE[rp * 2 + 1] + bE1;
                if (colO < 10)     o[colO] = dcO[rp * 2 + 0] + bO0;
                if (colO + 1 < 10) o[colO + 1] = dcO[rp * 2 + 1] + bO1;
            }
        }
    }
}

extern "C" void kernel_launch(void* const* d_in, const int* in_sizes, int n_in,
                              void* d_out, int out_size) {
    const float* obs   = (const float*)d_in[0];
    const float* hid   = (const float*)d_in[1];
    const float* enc_w = (const float*)d_in[2];
    const float* enc_b = (const float*)d_in[3];
    const float* w_ih  = (const float*)d_in[4];
    const float* w_hh  = (const float*)d_in[5];
    const float* b_ih  = (const float*)d_in[6];
    const float* b_hh  = (const float*)d_in[7];
    const float* v_w   = (const float*)d_in[20];
    const float* v_b   = (const float*)d_in[21];
    const float* dec_w = (const float*)d_in[22];
    const float* dec_b = (const float*)d_in[23];

    float* out  = (float*)d_out;
    float* hout = out + (size_t)SZ * 10;

    prep_kernel<<<(FRAG_TOTAL + 255) / 256, 256>>>(enc_w, w_ih, w_hh, v_w, dec_w);

    cudaFuncSetAttribute(ac_mma_kernel, cudaFuncAttributeMaxDynamicSharedMemorySize, SMEM_TOTAL);
    ac_mma_kernel<<<GRID, THREADS, SMEM_TOTAL>>>(obs, hid, enc_b, b_ih, b_hh, v_b, dec_b, out, hout);
}